// round 10
// baseline (speedup 1.0000x reference)
#include <cuda_runtime.h>
#include <cuda_fp16.h>
#include <cstddef>

#define FULLMASK 0xffffffffu

// exp(v/1000) 2nd-order Taylor: 1 + v*1e-3 + v^2*5e-7  (|v|<=~5.5 -> rel err < 3e-8)
#define EA1 1.0e-3f
#define EA2 5.0e-7f
// softplus(log(e-1-0.001) + da/1000) + 0.001, quadratic in da
#define SPC0 1.00063205286f
#define SPC1 6.319852e-4f
#define SPC2 1.162901e-7f
#define SCL  1.0e-3f

#define DSC   4096.0f          // delta scale (fp16 headroom)
#define IDSC  2.44140625e-4f   // 1/4096
#define UMEAN 0.0625f          // 1/16

__device__ __forceinline__ float tay(float t) {
    return fmaf(t, fmaf(t, EA2, EA1), 1.0f);
}
__device__ __forceinline__ float dot4(float4 a, float4 b) {
    return fmaf(a.x, b.x, fmaf(a.y, b.y, fmaf(a.z, b.z, a.w * b.w)));
}
// Distributed 4-lane reduce: lane q of each xor{1,2}-quad ends with the FULL
// quad-sum of slot q (i.e. row g4+4q). 3 shuffles.
__device__ __forceinline__ float dist4(float P0, float P1, float P2, float P3, int q) {
    const bool b0 = (q & 1) != 0;
    const float keepA = b0 ? P1 : P0;
    const float sendA = b0 ? P0 : P1;
    const float keepB = b0 ? P3 : P2;
    const float sendB = b0 ? P2 : P3;
    const float sAB = keepA + __shfl_xor_sync(FULLMASK, sendA, 1);
    const float sCD = keepB + __shfl_xor_sync(FULLMASK, sendB, 1);
    const bool b1 = (q & 2) != 0;
    const float keep2 = b1 ? sCD : sAB;
    const float send2 = b1 ? sAB : sCD;
    return keep2 + __shfl_xor_sync(FULLMASK, send2, 2);
}

// One batch element per 16-lane group; 2 elements/warp; 8 per 128-thread block.
// Lane o owns quarter (o&3) of rows {o>>2, +4, +8, +12}; after the distributed
// reduce it owns ALL row-scalars of row sti = (o>>2) + 4*(o&3) (no swap needed).
__global__ __launch_bounds__(128)
void dsit_kernel(const float* __restrict__ x,
                 const float* __restrict__ h,
                 float* __restrict__ z_out,
                 float* __restrict__ ld_out,
                 int batch)
{
    // fp16 MMA tiles: 16 rows x 24-half stride (48B rows, conflict-free STS/ldmatrix).
    __shared__ __align__(16) __half wA_sh[8 * 384];   // A = raw exp(dw/1000)
    __shared__ __align__(16) __half dB_sh[8 * 384];   // B = d' (k-major)
    __shared__ __align__(16) float c_sh[8][16];
    __shared__ __align__(16) float g_sh[8][16];
    __shared__ __align__(16) float k1_sh[8][16];
    __shared__ __align__(16) float S_sh[8][16];       // raw ps = ew . p

    const int tid = threadIdx.x;
    const int l   = tid & 31;     // lane
    const int e   = tid >> 4;     // element slot in block (0..7)
    const int o   = tid & 15;     // lane-within-element
    const int q   = o & 3;        // quarter (column group)
    const int g4  = o >> 2;       // row-group base
    const int sti = g4 + 4 * q;   // the row this lane owns after dist4
    int b = blockIdx.x * 8 + e;
    if (b >= batch) b = batch - 1;     // duplicate-work clamp, warp stays convergent

    const float* hb = h + (size_t)b * 544;

    // ---- front-batched, COALESCED global loads ----
    const float4* pdu = reinterpret_cast<const float4*>(hb + 288);
    const float4* pdw = reinterpret_cast<const float4*>(hb + 32);
    float4 du[4], dw[4];
#pragma unroll
    for (int t = 0; t < 4; t++) du[t] = pdu[o + 16 * t];
#pragma unroll
    for (int t = 0; t < 4; t++) dw[t] = pdw[o + 16 * t];
    const float da = hb[sti];          // row-sti scalars (same warp footprint)
    const float db = hb[16 + sti];
    const float4 x4 = *reinterpret_cast<const float4*>(x + (size_t)b * 16 + 4 * q);

    // ---- w: RAW exp quarters (no normalization); A tile + row-sum partials ----
    float4 ew[4];
    float  SwP[4];
#pragma unroll
    for (int t = 0; t < 4; t++) {
        ew[t].x = tay(dw[t].x); ew[t].y = tay(dw[t].y);
        ew[t].z = tay(dw[t].z); ew[t].w = tay(dw[t].w);
        SwP[t] = (ew[t].x + ew[t].y) + (ew[t].z + ew[t].w);
        __half2 h0 = __floats2half2_rn(ew[t].x, ew[t].y);
        __half2 h1 = __floats2half2_rn(ew[t].z, ew[t].w);
        uint2 v;
        v.x = *reinterpret_cast<unsigned*>(&h0);
        v.y = *reinterpret_cast<unsigned*>(&h1);
        *reinterpret_cast<uint2*>(&wA_sh[e * 384 + (g4 + 4 * t) * 24 + q * 4]) = v;
    }

    // ---- u: raw exp quarters + row-sum / x-dot partials ----
    float4 uu[4];
    float  SuP[4], pxP[4];
#pragma unroll
    for (int t = 0; t < 4; t++) {
        uu[t].x = tay(du[t].x); uu[t].y = tay(du[t].y);
        uu[t].z = tay(du[t].z); uu[t].w = tay(du[t].w);
        SuP[t] = (uu[t].x + uu[t].y) + (uu[t].z + uu[t].w);
        pxP[t] = dot4(uu[t], x4);
    }

    // ---- distributed reduces: this lane now holds row-sti scalars ----
    const float su_r = dist4(SuP[0], SuP[1], SuP[2], SuP[3], q);
    const float px_r = dist4(pxP[0], pxP[1], pxP[2], pxP[3], q);
    const float sw_r = dist4(SwP[0], SwP[1], SwP[2], SwP[3], q);

    // ---- row-sti scalar chain ----
    const float rcs = __fdividef(1.f, su_r);
    const float ux  = px_r * rcs;
    const float av  = fmaf(da, fmaf(da, SPC2, SPC1), SPC0);
    const float bv  = db * SCL;
    const float pre = fmaf(av, ux, bv);
    const float cc  = __fdividef(1.f, 1.f + __expf(-pre));
    const float qs  = __fdividef(1.f, 1.f + __expf(-cc));
    const float pv  = av * qs * (1.f - qs);
    const float lsw = __logf(sw_r);           // per-row log Sw (normalization fold)
    c_sh[e][sti]  = cc;
    g_sh[e][sti]  = pv;
    k1_sh[e][sti] = DSC * pv * rcs;
    __syncwarp(FULLMASK);

    // ---- B tile (delta') + raw dv/Sv quarter dots ----
    const float4 c4 = *reinterpret_cast<const float4*>(&c_sh[e][4 * q]);
    const float4 p4 = *reinterpret_cast<const float4*>(&g_sh[e][4 * q]);
    float pdP[4], psP[4];
#pragma unroll
    for (int t = 0; t < 4; t++) {
        const int r = g4 + 4 * t;
        const float k1 = k1_sh[e][r];
        const float t0 = -256.f * g_sh[e][r];    // -DSC*p/16
        __half2 h0 = __floats2half2_rn(fmaf(k1, uu[t].x, t0), fmaf(k1, uu[t].y, t0));
        __half2 h1 = __floats2half2_rn(fmaf(k1, uu[t].z, t0), fmaf(k1, uu[t].w, t0));
        uint2 v;
        v.x = *reinterpret_cast<unsigned*>(&h0);
        v.y = *reinterpret_cast<unsigned*>(&h1);
        *reinterpret_cast<uint2*>(&dB_sh[e * 384 + r * 24 + q * 4]) = v;

        pdP[t] = dot4(ew[t], c4);    // raw (unnormalized) w dots
        psP[t] = dot4(ew[t], p4);
    }
    const float pd_r = dist4(pdP[0], pdP[1], pdP[2], pdP[3], q);
    const float ps_r = dist4(psP[0], psP[1], psP[2], psP[3], q);
    S_sh[e][sti] = ps_r;                       // raw S for row sti
    __syncwarp(FULLMASK);   // tiles + S visible

    // ---- z for row sti:  dv = pd/Sw  ->  z = log(pd / (Sw - pd)) ----
    const float zv = __logf(__fdividef(pd_r, sw_r - pd_r));
    const float zc = zv - lsw;                 // z minus log-Sw correction
    z_out[(size_t)b * 16 + sti] = zv;

    // ---- per-element 16x16x16 MMA on RAW tiles:  M_raw = S/16 + C/4096 ----
    const int e0 = (tid >> 5) * 2;             // first element of this warp
    const int lrow  = l & 15;
    const int lcoff = (l >> 4) * 8;
    const int crow0 = l >> 2;

    float lg[2];
#pragma unroll
    for (int t = 0; t < 2; t++) {
        const int em = e0 + t;
        unsigned aA = (unsigned)__cvta_generic_to_shared(&wA_sh[em * 384 + lrow * 24 + lcoff]);
        unsigned aB = (unsigned)__cvta_generic_to_shared(&dB_sh[em * 384 + lrow * 24 + lcoff]);
        unsigned a0, a1, a2, a3, b0, b1, b2, b3;
        asm volatile("ldmatrix.sync.aligned.m8n8.x4.shared.b16 {%0,%1,%2,%3}, [%4];"
                     : "=r"(a0), "=r"(a1), "=r"(a2), "=r"(a3) : "r"(aA));
        asm volatile("ldmatrix.sync.aligned.m8n8.x4.trans.shared.b16 {%0,%1,%2,%3}, [%4];"
                     : "=r"(b0), "=r"(b1), "=r"(b2), "=r"(b3) : "r"(aB));
        float c0 = 0.f, c1 = 0.f, c2 = 0.f, c3 = 0.f;   // n 0-7
        float d0 = 0.f, d1 = 0.f, d2 = 0.f, d3 = 0.f;   // n 8-15
        asm volatile("mma.sync.aligned.m16n8k16.row.col.f32.f16.f16.f32 "
                     "{%0,%1,%2,%3}, {%4,%5,%6,%7}, {%8,%9}, {%0,%1,%2,%3};"
                     : "+f"(c0), "+f"(c1), "+f"(c2), "+f"(c3)
                     : "r"(a0), "r"(a1), "r"(a2), "r"(a3), "r"(b0), "r"(b1));
        asm volatile("mma.sync.aligned.m16n8k16.row.col.f32.f16.f16.f32 "
                     "{%0,%1,%2,%3}, {%4,%5,%6,%7}, {%8,%9}, {%0,%1,%2,%3};"
                     : "+f"(d0), "+f"(d1), "+f"(d2), "+f"(d3)
                     : "r"(a0), "r"(a1), "r"(a2), "r"(a3), "r"(b2), "r"(b3));

        const float s0 = UMEAN * S_sh[em][crow0];
        const float s1 = UMEAN * S_sh[em][crow0 + 8];
        const float m0 = fmaf(c0, IDSC, s0), m1 = fmaf(c1, IDSC, s0);
        const float m2 = fmaf(c2, IDSC, s1), m3 = fmaf(c3, IDSC, s1);
        const float m4 = fmaf(d0, IDSC, s0), m5 = fmaf(d1, IDSC, s0);
        const float m6 = fmaf(d2, IDSC, s1), m7 = fmaf(d3, IDSC, s1);
        // product of 8 raw M-entries (~0.22 each -> ~5e-6, safe) then one log
        const float pr = ((m0 * m1) * (m2 * m3)) * ((m4 * m5) * (m6 * m7));
        lg[t] = __logf(pr);
    }

    // ---- merged reduce:  ld = sum_lanes( 16*zc + lg_half ) over 16-lane group ----
    lg[0] += __shfl_xor_sync(FULLMASK, lg[0], 16);
    lg[1] += __shfl_xor_sync(FULLMASK, lg[1], 16);
    float w = fmaf(16.f, zc, (l < 16) ? lg[0] : lg[1]);
#pragma unroll
    for (int m = 8; m >= 1; m >>= 1)
        w += __shfl_xor_sync(FULLMASK, w, m, 16);

    // ---- outputs ----
    if (o == 0)
        ld_out[b] = w;                         // lane 0 -> e0, lane 16 -> e1
}

extern "C" void kernel_launch(void* const* d_in, const int* in_sizes, int n_in,
                              void* d_out, int out_size)
{
    const float* x = (const float*)d_in[0];   // [B, 16]
    const float* h = (const float*)d_in[1];   // [B, 544]
    const int batch = in_sizes[0] / 16;

    float* z_out  = (float*)d_out;                  // [B,16]
    float* ld_out = z_out + (size_t)batch * 16;     // [B]

    const int blocks = (batch + 7) / 8;
    dsit_kernel<<<blocks, 128>>>(x, h, z_out, ld_out, batch);
}

// round 11
// speedup vs baseline: 1.0352x; 1.0352x over previous
#include <cuda_runtime.h>
#include <cuda_fp16.h>
#include <cstddef>

#define FULLMASK 0xffffffffu

// exp(v/1000) 2nd-order Taylor: 1 + v*1e-3 + v^2*5e-7  (|v|<=~5.5 -> rel err < 3e-8)
#define EA1 1.0e-3f
#define EA2 5.0e-7f
// 256*(exp(v/1000)-1) = v*(0.256 + v*1.28e-4)
#define EB1 0.256f
#define EB2 1.28e-4f
#define INV256 0.00390625f
// softplus(log(e-1-0.001) + da/1000) + 0.001, quadratic in da
#define SPC0 1.00063205286f
#define SPC1 6.319852e-4f
#define SPC2 1.162901e-7f
#define SCL  1.0e-3f

#define IDSC  2.44140625e-4f   // 1/4096

__device__ __forceinline__ float tay(float t) {
    return fmaf(t, fmaf(t, EA2, EA1), 1.0f);
}
__device__ __forceinline__ float dot4(float4 a, float4 b) {
    return fmaf(a.x, b.x, fmaf(a.y, b.y, fmaf(a.z, b.z, a.w * b.w)));
}
// Distributed 4-lane reduce: lane q of each xor{1,2}-quad ends with the FULL
// quad-sum of slot q (i.e. row g4+4q). 3 shuffles.
__device__ __forceinline__ float dist4(float P0, float P1, float P2, float P3, int q) {
    const bool b0 = (q & 1) != 0;
    const float keepA = b0 ? P1 : P0;
    const float sendA = b0 ? P0 : P1;
    const float keepB = b0 ? P3 : P2;
    const float sendB = b0 ? P2 : P3;
    const float sAB = keepA + __shfl_xor_sync(FULLMASK, sendA, 1);
    const float sCD = keepB + __shfl_xor_sync(FULLMASK, sendB, 1);
    const bool b1 = (q & 2) != 0;
    const float keep2 = b1 ? sCD : sAB;
    const float send2 = b1 ? sAB : sCD;
    return keep2 + __shfl_xor_sync(FULLMASK, send2, 2);
}

// One batch element per 16-lane group; 2 elements/warp; 4 per 64-thread block.
// Lane o owns quarter (o&3) of rows {o>>2,+4,+8,+12}; after dist4 it owns all
// row-scalars of row sti = (o>>2) + 4*(o&3).
__global__ __launch_bounds__(64)
void dsit_kernel(const float* __restrict__ x,
                 const float* __restrict__ h,
                 float* __restrict__ z_out,
                 float* __restrict__ ld_out,
                 int batch)
{
    // fp16 MMA tiles: 16 rows x 24-half stride (48B rows, conflict-free STS/ldmatrix).
    __shared__ __align__(16) __half wA_sh[4 * 384];   // A = ew * 16*kappa (col-scaled)
    __shared__ __align__(16) __half dB_sh[4 * 384];   // B = 256*eps (k-major)
    __shared__ __align__(16) float c_sh[4][16];
    __shared__ __align__(16) float kp_sh[4][16];      // kappa = p * rcs
    __shared__ __align__(16) float T_sh[4][16];       // T = ew_row . kappa

    const int tid = threadIdx.x;
    const int l   = tid & 31;     // lane
    const int e   = tid >> 4;     // element slot in block (0..3)
    const int o   = tid & 15;     // lane-within-element
    const int q   = o & 3;        // quarter (column group)
    const int g4  = o >> 2;       // row-group base
    const int sti = g4 + 4 * q;   // the row this lane owns after dist4
    int b = blockIdx.x * 4 + e;
    if (b >= batch) b = batch - 1;     // duplicate-work clamp, warp stays convergent

    const float* hb = h + (size_t)b * 544;

    // ---- front-batched, COALESCED global loads ----
    const float4* pdu = reinterpret_cast<const float4*>(hb + 288);
    const float4* pdw = reinterpret_cast<const float4*>(hb + 32);
    float4 du[4], dw[4];
#pragma unroll
    for (int t = 0; t < 4; t++) du[t] = pdu[o + 16 * t];
#pragma unroll
    for (int t = 0; t < 4; t++) dw[t] = pdw[o + 16 * t];
    const float da = hb[sti];
    const float db = hb[16 + sti];
    const float4 x4 = *reinterpret_cast<const float4*>(x + (size_t)b * 16 + 4 * q);

    // ---- w: RAW exp quarters; row-sum partials (A tile stored in phase 2) ----
    float4 ew[4];
    float  SwP[4];
#pragma unroll
    for (int t = 0; t < 4; t++) {
        ew[t].x = tay(dw[t].x); ew[t].y = tay(dw[t].y);
        ew[t].z = tay(dw[t].z); ew[t].w = tay(dw[t].w);
        SwP[t] = (ew[t].x + ew[t].y) + (ew[t].z + ew[t].w);
    }

    // ---- u: eps = 256*(E-1) -> B tile NOW; E for row-sum / x-dot partials ----
    float SuP[4], pxP[4];
#pragma unroll
    for (int t = 0; t < 4; t++) {
        float4 ep;
        ep.x = du[t].x * fmaf(du[t].x, EB2, EB1);
        ep.y = du[t].y * fmaf(du[t].y, EB2, EB1);
        ep.z = du[t].z * fmaf(du[t].z, EB2, EB1);
        ep.w = du[t].w * fmaf(du[t].w, EB2, EB1);
        float4 uu;
        uu.x = fmaf(ep.x, INV256, 1.f); uu.y = fmaf(ep.y, INV256, 1.f);
        uu.z = fmaf(ep.z, INV256, 1.f); uu.w = fmaf(ep.w, INV256, 1.f);
        SuP[t] = (uu.x + uu.y) + (uu.z + uu.w);
        pxP[t] = dot4(uu, x4);
        __half2 h0 = __floats2half2_rn(ep.x, ep.y);
        __half2 h1 = __floats2half2_rn(ep.z, ep.w);
        uint2 v;
        v.x = *reinterpret_cast<unsigned*>(&h0);
        v.y = *reinterpret_cast<unsigned*>(&h1);
        *reinterpret_cast<uint2*>(&dB_sh[e * 384 + (g4 + 4 * t) * 24 + q * 4]) = v;
    }
    // (uu/eps registers all dead here)

    // ---- distributed reduces: this lane now holds row-sti scalars ----
    const float su_r = dist4(SuP[0], SuP[1], SuP[2], SuP[3], q);
    const float px_r = dist4(pxP[0], pxP[1], pxP[2], pxP[3], q);
    const float sw_r = dist4(SwP[0], SwP[1], SwP[2], SwP[3], q);

    // ---- row-sti scalar chain ----
    const float rcs = __fdividef(1.f, su_r);
    const float ux  = px_r * rcs;
    const float av  = fmaf(da, fmaf(da, SPC2, SPC1), SPC0);
    const float bv  = db * SCL;
    const float pre = fmaf(av, ux, bv);
    const float cc  = __fdividef(1.f, 1.f + __expf(-pre));
    const float qs  = __fdividef(1.f, 1.f + __expf(-cc));
    const float pv  = av * qs * (1.f - qs);
    const float lsw = __logf(sw_r);            // per-row log Sw (normalization fold)
    c_sh[e][sti]  = cc;
    kp_sh[e][sti] = pv * rcs;                  // kappa
    __syncwarp(FULLMASK);

    // ---- phase 2: A tile (ew * 16kappa, column-scaled) + pd/T quarter dots ----
    const float4 c4  = *reinterpret_cast<const float4*>(&c_sh[e][4 * q]);
    const float4 kp4 = *reinterpret_cast<const float4*>(&kp_sh[e][4 * q]);
    const float4 k16 = make_float4(16.f * kp4.x, 16.f * kp4.y, 16.f * kp4.z, 16.f * kp4.w);
    float pdP[4], TP[4];
#pragma unroll
    for (int t = 0; t < 4; t++) {
        __half2 h0 = __floats2half2_rn(ew[t].x * k16.x, ew[t].y * k16.y);
        __half2 h1 = __floats2half2_rn(ew[t].z * k16.z, ew[t].w * k16.w);
        uint2 v;
        v.x = *reinterpret_cast<unsigned*>(&h0);
        v.y = *reinterpret_cast<unsigned*>(&h1);
        *reinterpret_cast<uint2*>(&wA_sh[e * 384 + (g4 + 4 * t) * 24 + q * 4]) = v;

        pdP[t] = dot4(ew[t], c4);     // raw (unnormalized) w dots
        TP[t]  = dot4(ew[t], kp4);    // mean term
    }
    const float pd_r = dist4(pdP[0], pdP[1], pdP[2], pdP[3], q);
    const float T_r  = dist4(TP[0], TP[1], TP[2], TP[3], q);
    T_sh[e][sti] = T_r;
    __syncwarp(FULLMASK);   // tiles + T visible

    // ---- z for row sti:  dv = pd/Sw  ->  z = log(pd / (Sw - pd)) ----
    const float zv = __logf(__fdividef(pd_r, sw_r - pd_r));
    const float zc = zv - lsw;                 // z minus log-Sw correction
    z_out[(size_t)b * 16 + sti] = zv;

    // ---- per-element 16x16x16 MMA:  M_raw = T + C/4096 ----
    const int e0 = (tid >> 5) * 2;             // first element of this warp
    const int lrow  = l & 15;
    const int lcoff = (l >> 4) * 8;
    const int crow0 = l >> 2;

    float lg[2];
#pragma unroll
    for (int t = 0; t < 2; t++) {
        const int em = e0 + t;
        unsigned aA = (unsigned)__cvta_generic_to_shared(&wA_sh[em * 384 + lrow * 24 + lcoff]);
        unsigned aB = (unsigned)__cvta_generic_to_shared(&dB_sh[em * 384 + lrow * 24 + lcoff]);
        unsigned a0, a1, a2, a3, b0, b1, b2, b3;
        asm volatile("ldmatrix.sync.aligned.m8n8.x4.shared.b16 {%0,%1,%2,%3}, [%4];"
                     : "=r"(a0), "=r"(a1), "=r"(a2), "=r"(a3) : "r"(aA));
        asm volatile("ldmatrix.sync.aligned.m8n8.x4.trans.shared.b16 {%0,%1,%2,%3}, [%4];"
                     : "=r"(b0), "=r"(b1), "=r"(b2), "=r"(b3) : "r"(aB));
        float c0 = 0.f, c1 = 0.f, c2 = 0.f, c3 = 0.f;   // n 0-7
        float d0 = 0.f, d1 = 0.f, d2 = 0.f, d3 = 0.f;   // n 8-15
        asm volatile("mma.sync.aligned.m16n8k16.row.col.f32.f16.f16.f32 "
                     "{%0,%1,%2,%3}, {%4,%5,%6,%7}, {%8,%9}, {%0,%1,%2,%3};"
                     : "+f"(c0), "+f"(c1), "+f"(c2), "+f"(c3)
                     : "r"(a0), "r"(a1), "r"(a2), "r"(a3), "r"(b0), "r"(b1));
        asm volatile("mma.sync.aligned.m16n8k16.row.col.f32.f16.f16.f32 "
                     "{%0,%1,%2,%3}, {%4,%5,%6,%7}, {%8,%9}, {%0,%1,%2,%3};"
                     : "+f"(d0), "+f"(d1), "+f"(d2), "+f"(d3)
                     : "r"(a0), "r"(a1), "r"(a2), "r"(a3), "r"(b2), "r"(b3));

        const float s0 = T_sh[em][crow0];
        const float s1 = T_sh[em][crow0 + 8];
        const float m0 = fmaf(c0, IDSC, s0), m1 = fmaf(c1, IDSC, s0);
        const float m2 = fmaf(c2, IDSC, s1), m3 = fmaf(c3, IDSC, s1);
        const float m4 = fmaf(d0, IDSC, s0), m5 = fmaf(d1, IDSC, s0);
        const float m6 = fmaf(d2, IDSC, s1), m7 = fmaf(d3, IDSC, s1);
        // product of 8 raw M-entries (~0.22 each -> ~5e-6, safe) then one log
        const float pr = ((m0 * m1) * (m2 * m3)) * ((m4 * m5) * (m6 * m7));
        lg[t] = __logf(pr);
    }

    // ---- merged reduce:  ld = sum_lanes( 16*zc + lg_half ) over 16-lane group ----
    lg[0] += __shfl_xor_sync(FULLMASK, lg[0], 16);
    lg[1] += __shfl_xor_sync(FULLMASK, lg[1], 16);
    float w = fmaf(16.f, zc, (l < 16) ? lg[0] : lg[1]);
#pragma unroll
    for (int m = 8; m >= 1; m >>= 1)
        w += __shfl_xor_sync(FULLMASK, w, m, 16);

    // ---- outputs ----
    if (o == 0)
        ld_out[b] = w;                         // lane 0 -> e0, lane 16 -> e1

}

extern "C" void kernel_launch(void* const* d_in, const int* in_sizes, int n_in,
                              void* d_out, int out_size)
{
    const float* x = (const float*)d_in[0];   // [B, 16]
    const float* h = (const float*)d_in[1];   // [B, 544]
    const int batch = in_sizes[0] / 16;

    float* z_out  = (float*)d_out;                  // [B,16]
    float* ld_out = z_out + (size_t)batch * 16;     // [B]

    const int blocks = (batch + 3) / 4;
    dsit_kernel<<<blocks, 64>>>(x, h, z_out, ld_out, batch);
}